// round 12
// baseline (speedup 1.0000x reference)
#include <cuda_runtime.h>

// TransOp_expm via traceless Cayley-Hamilton, SCALAR fp32, ONE batch per
// thread (max occupancy, warp-parallel latency hiding — issue% is monotone
// decreasing in batches/thread: 73/63/52 for 1/2/4). NSQ=3, ORDER=10.
// __launch_bounds__(256,8): 32-reg cap -> 64 warps/SM theoretical.

#define NSQ 3
#define NORD 10

__global__ __launch_bounds__(256, 8) void expmsc1_kernel(
    const float* __restrict__ x,
    const float* __restrict__ c,
    const float* __restrict__ psi,
    float* __restrict__ out,
    int B)
{
    // psi pre-scaled by 1/2^NSQ; rows padded to 12 floats (16B-aligned)
    __shared__ __align__(16) float s_psi[72];
    if (threadIdx.x < 72) {
        int row = threadIdx.x / 12, col = threadIdx.x % 12;
        s_psi[threadIdx.x] =
            (col < 9) ? psi[row * 9 + col] * (1.0f / (float)(1 << NSQ)) : 0.0f;
    }
    __syncthreads();

    int b = blockIdx.x * blockDim.x + threadIdx.x;
    if (b >= B) return;

    // ---- loads: c (3 x LDG.64), x (3 x LDG.32) ----
    float cm0, cm1, cm2, cm3, cm4, cm5;
    {
        const float2* cq = (const float2*)(c + b * 6);
        float2 a = __ldg(&cq[0]);
        float2 d = __ldg(&cq[1]);
        float2 e = __ldg(&cq[2]);
        cm0 = a.x; cm1 = a.y; cm2 = d.x; cm3 = d.y; cm4 = e.x; cm5 = e.y;
    }
    const float* xb = x + b * 3;
    float v0 = __ldg(&xb[0]), v1 = __ldg(&xb[1]), v2 = __ldg(&xb[2]);

    // ---- A = sum_m c_m * psi_scaled[m] ----
    float A0, A1, A2, A3, A4, A5, A6, A7, A8;
    {
        const float4* pr = (const float4*)s_psi;
        float4 p0 = pr[0], p1 = pr[1];
        float  p8 = s_psi[8];
        A0 = cm0 * p0.x; A1 = cm0 * p0.y; A2 = cm0 * p0.z; A3 = cm0 * p0.w;
        A4 = cm0 * p1.x; A5 = cm0 * p1.y; A6 = cm0 * p1.z; A7 = cm0 * p1.w;
        A8 = cm0 * p8;
        float cms[5] = {cm1, cm2, cm3, cm4, cm5};
        #pragma unroll
        for (int m = 1; m < 6; m++) {
            float4 q0 = pr[m * 3 + 0];
            float4 q1 = pr[m * 3 + 1];
            float  q8 = s_psi[m * 12 + 8];
            float cmm = cms[m - 1];
            A0 = fmaf(cmm, q0.x, A0); A1 = fmaf(cmm, q0.y, A1);
            A2 = fmaf(cmm, q0.z, A2); A3 = fmaf(cmm, q0.w, A3);
            A4 = fmaf(cmm, q1.x, A4); A5 = fmaf(cmm, q1.y, A5);
            A6 = fmaf(cmm, q1.z, A6); A7 = fmaf(cmm, q1.w, A7);
            A8 = fmaf(cmm, q8,   A8);
        }
    }

    // ---- trace prefactor + traceless shift ----
    float c1 = A0 + A4 + A8;
    float emu = __expf(c1 * ((float)(1 << NSQ) / 3.0f));
    float mu = c1 * (1.0f / 3.0f);
    A0 -= mu; A4 -= mu; A8 -= mu;

    // ---- invariants of traceless Ab ----
    float tt = fmaf(A2, A6, A1 * A3);
    tt = fmaf(A5, A7, tt);
    float ss = fmaf(A4, A4, A0 * A0);
    ss = fmaf(A8, A8, ss);
    float nc2 = fmaf(ss, 0.5f, tt);             // -c2 = tr(Ab^2)/2

    float m0  = fmaf(A4, A8, -(A5 * A7));
    float m1n = fmaf(A5, A6, -(A3 * A8));
    float m2  = fmaf(A3, A7, -(A4 * A6));
    float c3  = fmaf(A0, m0, fmaf(A1, m1n, A2 * m2));   // det(Ab)

    // ---- matvecs (A dies after this) ----
    float w0 = fmaf(A0, v0, fmaf(A1, v1, A2 * v2));
    float w1 = fmaf(A3, v0, fmaf(A4, v1, A5 * v2));
    float w2 = fmaf(A6, v0, fmaf(A7, v1, A8 * v2));
    float u0 = fmaf(A0, w0, fmaf(A1, w1, A2 * w2));
    float u1 = fmaf(A3, w0, fmaf(A4, w1, A5 * w2));
    float u2 = fmaf(A6, w0, fmaf(A7, w1, A8 * w2));

    // ---- Horner Taylor (traceless): E = sa I + sb Ab + sc Ab^2 ----
    const float invfact[NORD + 1] = {
        1.f, 1.f, 0.5f, 1.f/6.f, 1.f/24.f, 1.f/120.f, 1.f/720.f,
        1.f/5040.f, 1.f/40320.f, 1.f/362880.f, 1.f/3628800.f
    };
    float sa = invfact[NORD], sb = 0.0f, sc = 0.0f;
    #pragma unroll
    for (int k = NORD - 1; k >= 0; k--) {
        float oc = sc;
        float na = fmaf(c3,  oc, invfact[k]);
        float nb = fmaf(nc2, oc, sa);
        sc = sb;
        sa = na;
        sb = nb;
    }

    // ---- squarings (Ab^3 = nc2 Ab + c3 I) ----
    #pragma unroll
    for (int sq = 0; sq < NSQ; sq++) {
        float bc2 = 2.0f * (sb * sc);
        float cc  = sc * sc;
        float ab2 = 2.0f * (sa * sb);
        float ac2 = 2.0f * (sa * sc);
        float na  = fmaf(bc2, c3, sa * sa);
        float nb  = fmaf(cc, c3, fmaf(bc2, nc2, ab2));
        float ncc = fmaf(cc, nc2, fmaf(sb, sb, ac2));
        sa = na; sb = nb; sc = ncc;
    }

    // ---- y = emu * (sa v + sb w + sc u) ----
    sa *= emu; sb *= emu; sc *= emu;
    float* ob = out + b * 3;
    ob[0] = fmaf(sa, v0, fmaf(sb, w0, sc * u0));
    ob[1] = fmaf(sa, v1, fmaf(sb, w1, sc * u1));
    ob[2] = fmaf(sa, v2, fmaf(sb, w2, sc * u2));
}

extern "C" void kernel_launch(void* const* d_in, const int* in_sizes, int n_in,
                              void* d_out, int out_size) {
    const float* x   = (const float*)d_in[0];  // [B,3,1]
    const float* c   = (const float*)d_in[1];  // [B,6]
    const float* psi = (const float*)d_in[2];  // [6,3,3]
    float* out = (float*)d_out;                // [B,3]

    int B = in_sizes[0] / 3;
    int threads = 256;
    int blocks = (B + threads - 1) / threads;
    expmsc1_kernel<<<blocks, threads>>>(x, c, psi, out, B);
}

// round 13
// speedup vs baseline: 1.0879x; 1.0879x over previous
#include <cuda_runtime.h>

// TransOp_expm via traceless Cayley-Hamilton, SCALAR fp32, one batch/thread.
// R13: NSQ=2 / NORD=12 — ||A||max ~ 1.6 (chi_6 max over 2^21 ~ 6.3, /4),
// truncation ~2e-6 < fp32 floor. One fewer squaring shortens the serial
// chain all warps phase-lock on. __launch_bounds__(256,8): 32-reg cap.

#define NSQ 2
#define NORD 12

__global__ __launch_bounds__(256, 8) void expmsc13_kernel(
    const float* __restrict__ x,
    const float* __restrict__ c,
    const float* __restrict__ psi,
    float* __restrict__ out,
    int B)
{
    // psi pre-scaled by 1/2^NSQ; rows padded to 12 floats (16B-aligned)
    __shared__ __align__(16) float s_psi[72];
    if (threadIdx.x < 72) {
        int row = threadIdx.x / 12, col = threadIdx.x % 12;
        s_psi[threadIdx.x] =
            (col < 9) ? psi[row * 9 + col] * (1.0f / (float)(1 << NSQ)) : 0.0f;
    }
    __syncthreads();

    int b = blockIdx.x * blockDim.x + threadIdx.x;
    if (b >= B) return;

    // ---- loads: c (3 x LDG.64), x (3 x LDG.32) ----
    float cm0, cm1, cm2, cm3, cm4, cm5;
    {
        const float2* cq = (const float2*)(c + b * 6);
        float2 a = __ldg(&cq[0]);
        float2 d = __ldg(&cq[1]);
        float2 e = __ldg(&cq[2]);
        cm0 = a.x; cm1 = a.y; cm2 = d.x; cm3 = d.y; cm4 = e.x; cm5 = e.y;
    }
    const float* xb = x + b * 3;
    float v0 = __ldg(&xb[0]), v1 = __ldg(&xb[1]), v2 = __ldg(&xb[2]);

    // ---- A = sum_m c_m * psi_scaled[m] ----
    float A0, A1, A2, A3, A4, A5, A6, A7, A8;
    {
        const float4* pr = (const float4*)s_psi;
        float4 p0 = pr[0], p1 = pr[1];
        float  p8 = s_psi[8];
        A0 = cm0 * p0.x; A1 = cm0 * p0.y; A2 = cm0 * p0.z; A3 = cm0 * p0.w;
        A4 = cm0 * p1.x; A5 = cm0 * p1.y; A6 = cm0 * p1.z; A7 = cm0 * p1.w;
        A8 = cm0 * p8;
        float cms[5] = {cm1, cm2, cm3, cm4, cm5};
        #pragma unroll
        for (int m = 1; m < 6; m++) {
            float4 q0 = pr[m * 3 + 0];
            float4 q1 = pr[m * 3 + 1];
            float  q8 = s_psi[m * 12 + 8];
            float cmm = cms[m - 1];
            A0 = fmaf(cmm, q0.x, A0); A1 = fmaf(cmm, q0.y, A1);
            A2 = fmaf(cmm, q0.z, A2); A3 = fmaf(cmm, q0.w, A3);
            A4 = fmaf(cmm, q1.x, A4); A5 = fmaf(cmm, q1.y, A5);
            A6 = fmaf(cmm, q1.z, A6); A7 = fmaf(cmm, q1.w, A7);
            A8 = fmaf(cmm, q8,   A8);
        }
    }

    // ---- trace prefactor + traceless shift ----
    float c1 = A0 + A4 + A8;
    float emu = __expf(c1 * ((float)(1 << NSQ) / 3.0f));
    float mu = c1 * (1.0f / 3.0f);
    A0 -= mu; A4 -= mu; A8 -= mu;

    // ---- invariants of traceless Ab ----
    float tt = fmaf(A2, A6, A1 * A3);
    tt = fmaf(A5, A7, tt);
    float ss = fmaf(A4, A4, A0 * A0);
    ss = fmaf(A8, A8, ss);
    float nc2 = fmaf(ss, 0.5f, tt);             // -c2 = tr(Ab^2)/2

    float m0  = fmaf(A4, A8, -(A5 * A7));
    float m1n = fmaf(A5, A6, -(A3 * A8));
    float m2  = fmaf(A3, A7, -(A4 * A6));
    float c3  = fmaf(A0, m0, fmaf(A1, m1n, A2 * m2));   // det(Ab)

    // ---- matvecs (A dies after this) ----
    float w0 = fmaf(A0, v0, fmaf(A1, v1, A2 * v2));
    float w1 = fmaf(A3, v0, fmaf(A4, v1, A5 * v2));
    float w2 = fmaf(A6, v0, fmaf(A7, v1, A8 * v2));
    float u0 = fmaf(A0, w0, fmaf(A1, w1, A2 * w2));
    float u1 = fmaf(A3, w0, fmaf(A4, w1, A5 * w2));
    float u2 = fmaf(A6, w0, fmaf(A7, w1, A8 * w2));

    // ---- Horner Taylor (traceless): E = sa I + sb Ab + sc Ab^2 ----
    const float invfact[NORD + 1] = {
        1.f, 1.f, 0.5f, 1.f/6.f, 1.f/24.f, 1.f/120.f, 1.f/720.f,
        1.f/5040.f, 1.f/40320.f, 1.f/362880.f, 1.f/3628800.f,
        1.f/39916800.f, 1.f/479001600.f
    };
    float sa = invfact[NORD], sb = 0.0f, sc = 0.0f;
    #pragma unroll
    for (int k = NORD - 1; k >= 0; k--) {
        float oc = sc;
        float na = fmaf(c3,  oc, invfact[k]);
        float nb = fmaf(nc2, oc, sa);
        sc = sb;
        sa = na;
        sb = nb;
    }

    // ---- squarings (Ab^3 = nc2 Ab + c3 I) ----
    #pragma unroll
    for (int sq = 0; sq < NSQ; sq++) {
        float bc2 = 2.0f * (sb * sc);
        float cc  = sc * sc;
        float ab2 = 2.0f * (sa * sb);
        float ac2 = 2.0f * (sa * sc);
        float na  = fmaf(bc2, c3, sa * sa);
        float nb  = fmaf(cc, c3, fmaf(bc2, nc2, ab2));
        float ncc = fmaf(cc, nc2, fmaf(sb, sb, ac2));
        sa = na; sb = nb; sc = ncc;
    }

    // ---- y = emu * (sa v + sb w + sc u) ----
    sa *= emu; sb *= emu; sc *= emu;
    float* ob = out + b * 3;
    ob[0] = fmaf(sa, v0, fmaf(sb, w0, sc * u0));
    ob[1] = fmaf(sa, v1, fmaf(sb, w1, sc * u1));
    ob[2] = fmaf(sa, v2, fmaf(sb, w2, sc * u2));
}

extern "C" void kernel_launch(void* const* d_in, const int* in_sizes, int n_in,
                              void* d_out, int out_size) {
    const float* x   = (const float*)d_in[0];  // [B,3,1]
    const float* c   = (const float*)d_in[1];  // [B,6]
    const float* psi = (const float*)d_in[2];  // [6,3,3]
    float* out = (float*)d_out;                // [B,3]

    int B = in_sizes[0] / 3;
    int threads = 256;
    int blocks = (B + threads - 1) / threads;
    expmsc13_kernel<<<blocks, threads>>>(x, c, psi, out, B);
}

// round 14
// speedup vs baseline: 1.1512x; 1.0581x over previous
#include <cuda_runtime.h>

// TransOp_expm via traceless Cayley-Hamilton, SCALAR fp32, one batch/thread
// per iteration, SINGLE-WAVE grid-stride (1184 CTAs = 148 SMs x 8 resident).
// Kills per-CTA cold-start LDG stalls (paid once, not 7x) and wave
// transitions. NSQ=2, ORDER=12.

#define NSQ 2
#define NORD 12

__global__ __launch_bounds__(256, 8) void expmsc14_kernel(
    const float* __restrict__ x,
    const float* __restrict__ c,
    const float* __restrict__ psi,
    float* __restrict__ out,
    int B)
{
    // psi pre-scaled by 1/2^NSQ; rows padded to 12 floats (16B-aligned)
    __shared__ __align__(16) float s_psi[72];
    if (threadIdx.x < 72) {
        int row = threadIdx.x / 12, col = threadIdx.x % 12;
        s_psi[threadIdx.x] =
            (col < 9) ? psi[row * 9 + col] * (1.0f / (float)(1 << NSQ)) : 0.0f;
    }
    __syncthreads();

    const int stride = gridDim.x * blockDim.x;

    for (int b = blockIdx.x * blockDim.x + threadIdx.x; b < B; b += stride) {
        // ---- loads: c (3 x LDG.64), x (3 x LDG.32) ----
        float cm0, cm1, cm2, cm3, cm4, cm5;
        {
            const float2* cq = (const float2*)(c + b * 6);
            float2 a = __ldg(&cq[0]);
            float2 d = __ldg(&cq[1]);
            float2 e = __ldg(&cq[2]);
            cm0 = a.x; cm1 = a.y; cm2 = d.x; cm3 = d.y; cm4 = e.x; cm5 = e.y;
        }
        const float* xb = x + b * 3;
        float v0 = __ldg(&xb[0]), v1 = __ldg(&xb[1]), v2 = __ldg(&xb[2]);

        // ---- A = sum_m c_m * psi_scaled[m] ----
        float A0, A1, A2, A3, A4, A5, A6, A7, A8;
        {
            const float4* pr = (const float4*)s_psi;
            float4 p0 = pr[0], p1 = pr[1];
            float  p8 = s_psi[8];
            A0 = cm0 * p0.x; A1 = cm0 * p0.y; A2 = cm0 * p0.z; A3 = cm0 * p0.w;
            A4 = cm0 * p1.x; A5 = cm0 * p1.y; A6 = cm0 * p1.z; A7 = cm0 * p1.w;
            A8 = cm0 * p8;
            float cms[5] = {cm1, cm2, cm3, cm4, cm5};
            #pragma unroll
            for (int m = 1; m < 6; m++) {
                float4 q0 = pr[m * 3 + 0];
                float4 q1 = pr[m * 3 + 1];
                float  q8 = s_psi[m * 12 + 8];
                float cmm = cms[m - 1];
                A0 = fmaf(cmm, q0.x, A0); A1 = fmaf(cmm, q0.y, A1);
                A2 = fmaf(cmm, q0.z, A2); A3 = fmaf(cmm, q0.w, A3);
                A4 = fmaf(cmm, q1.x, A4); A5 = fmaf(cmm, q1.y, A5);
                A6 = fmaf(cmm, q1.z, A6); A7 = fmaf(cmm, q1.w, A7);
                A8 = fmaf(cmm, q8,   A8);
            }
        }

        // ---- trace prefactor + traceless shift ----
        float c1 = A0 + A4 + A8;
        float emu = __expf(c1 * ((float)(1 << NSQ) / 3.0f));
        float mu = c1 * (1.0f / 3.0f);
        A0 -= mu; A4 -= mu; A8 -= mu;

        // ---- invariants of traceless Ab ----
        float tt = fmaf(A2, A6, A1 * A3);
        tt = fmaf(A5, A7, tt);
        float ss = fmaf(A4, A4, A0 * A0);
        ss = fmaf(A8, A8, ss);
        float nc2 = fmaf(ss, 0.5f, tt);             // -c2 = tr(Ab^2)/2

        float m0  = fmaf(A4, A8, -(A5 * A7));
        float m1n = fmaf(A5, A6, -(A3 * A8));
        float m2  = fmaf(A3, A7, -(A4 * A6));
        float c3  = fmaf(A0, m0, fmaf(A1, m1n, A2 * m2));   // det(Ab)

        // ---- matvecs (A dies after this) ----
        float w0 = fmaf(A0, v0, fmaf(A1, v1, A2 * v2));
        float w1 = fmaf(A3, v0, fmaf(A4, v1, A5 * v2));
        float w2 = fmaf(A6, v0, fmaf(A7, v1, A8 * v2));
        float u0 = fmaf(A0, w0, fmaf(A1, w1, A2 * w2));
        float u1 = fmaf(A3, w0, fmaf(A4, w1, A5 * w2));
        float u2 = fmaf(A6, w0, fmaf(A7, w1, A8 * w2));

        // ---- Horner Taylor (traceless): E = sa I + sb Ab + sc Ab^2 ----
        const float invfact[NORD + 1] = {
            1.f, 1.f, 0.5f, 1.f/6.f, 1.f/24.f, 1.f/120.f, 1.f/720.f,
            1.f/5040.f, 1.f/40320.f, 1.f/362880.f, 1.f/3628800.f,
            1.f/39916800.f, 1.f/479001600.f
        };
        float sa = invfact[NORD], sb = 0.0f, sc = 0.0f;
        #pragma unroll
        for (int k = NORD - 1; k >= 0; k--) {
            float oc = sc;
            float na = fmaf(c3,  oc, invfact[k]);
            float nb = fmaf(nc2, oc, sa);
            sc = sb;
            sa = na;
            sb = nb;
        }

        // ---- squarings (Ab^3 = nc2 Ab + c3 I) ----
        #pragma unroll
        for (int sq = 0; sq < NSQ; sq++) {
            float bc2 = 2.0f * (sb * sc);
            float cc  = sc * sc;
            float ab2 = 2.0f * (sa * sb);
            float ac2 = 2.0f * (sa * sc);
            float na  = fmaf(bc2, c3, sa * sa);
            float nb  = fmaf(cc, c3, fmaf(bc2, nc2, ab2));
            float ncc = fmaf(cc, nc2, fmaf(sb, sb, ac2));
            sa = na; sb = nb; sc = ncc;
        }

        // ---- y = emu * (sa v + sb w + sc u) ----
        sa *= emu; sb *= emu; sc *= emu;
        float* ob = out + b * 3;
        ob[0] = fmaf(sa, v0, fmaf(sb, w0, sc * u0));
        ob[1] = fmaf(sa, v1, fmaf(sb, w1, sc * u1));
        ob[2] = fmaf(sa, v2, fmaf(sb, w2, sc * u2));
    }
}

extern "C" void kernel_launch(void* const* d_in, const int* in_sizes, int n_in,
                              void* d_out, int out_size) {
    const float* x   = (const float*)d_in[0];  // [B,3,1]
    const float* c   = (const float*)d_in[1];  // [B,6]
    const float* psi = (const float*)d_in[2];  // [6,3,3]
    float* out = (float*)d_out;                // [B,3]

    int B = in_sizes[0] / 3;
    int threads = 256;
    int blocks = 148 * 8;                      // exactly one resident wave
    int needed = (B + threads - 1) / threads;
    if (needed < blocks) blocks = needed;
    expmsc14_kernel<<<blocks, threads>>>(x, c, psi, out, B);
}

// round 15
// speedup vs baseline: 1.2092x; 1.0504x over previous
#include <cuda_runtime.h>

// TransOp_expm via traceless Cayley-Hamilton, SCALAR fp32, one batch/thread
// per iteration, single-wave grid-stride + SOFTWARE PREFETCH: next
// iteration's c/x loads issue before the current batch's compute, so the
// ~300-600cyc memory latency hides under ~400cyc of fma work.
// NSQ=2, ORDER=12.

#define NSQ 2
#define NORD 12

__global__ __launch_bounds__(256, 6) void expmsc15_kernel(
    const float* __restrict__ x,
    const float* __restrict__ c,
    const float* __restrict__ psi,
    float* __restrict__ out,
    int B)
{
    // psi pre-scaled by 1/2^NSQ; rows padded to 12 floats (16B-aligned)
    __shared__ __align__(16) float s_psi[72];
    if (threadIdx.x < 72) {
        int row = threadIdx.x / 12, col = threadIdx.x % 12;
        s_psi[threadIdx.x] =
            (col < 9) ? psi[row * 9 + col] * (1.0f / (float)(1 << NSQ)) : 0.0f;
    }
    __syncthreads();

    const int stride = gridDim.x * blockDim.x;
    int b = blockIdx.x * blockDim.x + threadIdx.x;
    if (b >= B) return;

    // ---- prime: loads for first batch ----
    float2 ld_c0, ld_c1, ld_c2;
    float  ld_x0, ld_x1, ld_x2;
    {
        const float2* cq = (const float2*)(c + b * 6);
        ld_c0 = __ldg(&cq[0]);
        ld_c1 = __ldg(&cq[1]);
        ld_c2 = __ldg(&cq[2]);
        const float* xb = x + b * 3;
        ld_x0 = __ldg(&xb[0]); ld_x1 = __ldg(&xb[1]); ld_x2 = __ldg(&xb[2]);
    }

    while (true) {
        int pn = b + stride;
        bool has_next = (pn < B);
        int pc = has_next ? pn : b;     // clamp: harmless reload of current

        // ---- consume current into locals ----
        float cm0 = ld_c0.x, cm1 = ld_c0.y, cm2 = ld_c1.x;
        float cm3 = ld_c1.y, cm4 = ld_c2.x, cm5 = ld_c2.y;
        float v0 = ld_x0, v1 = ld_x1, v2 = ld_x2;

        // ---- prefetch next iteration (overlaps all compute below) ----
        {
            const float2* cq = (const float2*)(c + pc * 6);
            ld_c0 = __ldg(&cq[0]);
            ld_c1 = __ldg(&cq[1]);
            ld_c2 = __ldg(&cq[2]);
            const float* xb = x + pc * 3;
            ld_x0 = __ldg(&xb[0]); ld_x1 = __ldg(&xb[1]); ld_x2 = __ldg(&xb[2]);
        }

        // ---- A = sum_m c_m * psi_scaled[m] ----
        float A0, A1, A2, A3, A4, A5, A6, A7, A8;
        {
            const float4* pr = (const float4*)s_psi;
            float4 p0 = pr[0], p1 = pr[1];
            float  p8 = s_psi[8];
            A0 = cm0 * p0.x; A1 = cm0 * p0.y; A2 = cm0 * p0.z; A3 = cm0 * p0.w;
            A4 = cm0 * p1.x; A5 = cm0 * p1.y; A6 = cm0 * p1.z; A7 = cm0 * p1.w;
            A8 = cm0 * p8;
            float cms[5] = {cm1, cm2, cm3, cm4, cm5};
            #pragma unroll
            for (int m = 1; m < 6; m++) {
                float4 q0 = pr[m * 3 + 0];
                float4 q1 = pr[m * 3 + 1];
                float  q8 = s_psi[m * 12 + 8];
                float cmm = cms[m - 1];
                A0 = fmaf(cmm, q0.x, A0); A1 = fmaf(cmm, q0.y, A1);
                A2 = fmaf(cmm, q0.z, A2); A3 = fmaf(cmm, q0.w, A3);
                A4 = fmaf(cmm, q1.x, A4); A5 = fmaf(cmm, q1.y, A5);
                A6 = fmaf(cmm, q1.z, A6); A7 = fmaf(cmm, q1.w, A7);
                A8 = fmaf(cmm, q8,   A8);
            }
        }

        // ---- trace prefactor + traceless shift ----
        float c1 = A0 + A4 + A8;
        float emu = __expf(c1 * ((float)(1 << NSQ) / 3.0f));
        float mu = c1 * (1.0f / 3.0f);
        A0 -= mu; A4 -= mu; A8 -= mu;

        // ---- invariants of traceless Ab ----
        float tt = fmaf(A2, A6, A1 * A3);
        tt = fmaf(A5, A7, tt);
        float ss = fmaf(A4, A4, A0 * A0);
        ss = fmaf(A8, A8, ss);
        float nc2 = fmaf(ss, 0.5f, tt);             // -c2 = tr(Ab^2)/2

        float m0  = fmaf(A4, A8, -(A5 * A7));
        float m1n = fmaf(A5, A6, -(A3 * A8));
        float m2  = fmaf(A3, A7, -(A4 * A6));
        float c3  = fmaf(A0, m0, fmaf(A1, m1n, A2 * m2));   // det(Ab)

        // ---- matvecs (A dies after this) ----
        float w0 = fmaf(A0, v0, fmaf(A1, v1, A2 * v2));
        float w1 = fmaf(A3, v0, fmaf(A4, v1, A5 * v2));
        float w2 = fmaf(A6, v0, fmaf(A7, v1, A8 * v2));
        float u0 = fmaf(A0, w0, fmaf(A1, w1, A2 * w2));
        float u1 = fmaf(A3, w0, fmaf(A4, w1, A5 * w2));
        float u2 = fmaf(A6, w0, fmaf(A7, w1, A8 * w2));

        // ---- Horner Taylor (traceless): E = sa I + sb Ab + sc Ab^2 ----
        const float invfact[NORD + 1] = {
            1.f, 1.f, 0.5f, 1.f/6.f, 1.f/24.f, 1.f/120.f, 1.f/720.f,
            1.f/5040.f, 1.f/40320.f, 1.f/362880.f, 1.f/3628800.f,
            1.f/39916800.f, 1.f/479001600.f
        };
        float sa = invfact[NORD], sb = 0.0f, sc = 0.0f;
        #pragma unroll
        for (int k = NORD - 1; k >= 0; k--) {
            float oc = sc;
            float na = fmaf(c3,  oc, invfact[k]);
            float nb = fmaf(nc2, oc, sa);
            sc = sb;
            sa = na;
            sb = nb;
        }

        // ---- squarings (Ab^3 = nc2 Ab + c3 I) ----
        #pragma unroll
        for (int sq = 0; sq < NSQ; sq++) {
            float bc2 = 2.0f * (sb * sc);
            float cc  = sc * sc;
            float ab2 = 2.0f * (sa * sb);
            float ac2 = 2.0f * (sa * sc);
            float na  = fmaf(bc2, c3, sa * sa);
            float nb  = fmaf(cc, c3, fmaf(bc2, nc2, ab2));
            float ncc = fmaf(cc, nc2, fmaf(sb, sb, ac2));
            sa = na; sb = nb; sc = ncc;
        }

        // ---- y = emu * (sa v + sb w + sc u) ----
        sa *= emu; sb *= emu; sc *= emu;
        float* ob = out + b * 3;
        ob[0] = fmaf(sa, v0, fmaf(sb, w0, sc * u0));
        ob[1] = fmaf(sa, v1, fmaf(sb, w1, sc * u1));
        ob[2] = fmaf(sa, v2, fmaf(sb, w2, sc * u2));

        if (!has_next) break;
        b = pn;
    }
}

extern "C" void kernel_launch(void* const* d_in, const int* in_sizes, int n_in,
                              void* d_out, int out_size) {
    const float* x   = (const float*)d_in[0];  // [B,3,1]
    const float* c   = (const float*)d_in[1];  // [B,6]
    const float* psi = (const float*)d_in[2];  // [6,3,3]
    float* out = (float*)d_out;                // [B,3]

    int B = in_sizes[0] / 3;
    int threads = 256;
    int blocks = 148 * 6;                      // one resident wave at 6 CTA/SM
    int needed = (B + threads - 1) / threads;
    if (needed < blocks) blocks = needed;
    expmsc15_kernel<<<blocks, threads>>>(x, c, psi, out, B);
}